// round 1
// baseline (speedup 1.0000x reference)
#include <cuda_runtime.h>
#include <math.h>

// Problem constants
#define Bn 4
#define Tn 2048
#define Cn 1024
#define Hn 16
#define Dn 64
#define Mn (Bn*Tn)   // 8192 token rows

// Scratch (device globals; no allocation allowed)
__device__ float g_q[(size_t)Mn*Cn];
__device__ float g_k[(size_t)Mn*Cn];
__device__ float g_v[(size_t)Mn*Cn];
__device__ float g_att[(size_t)Mn*Cn];

// ---------------------------------------------------------------------------
// SGEMM: C[M,N] = A[M,K] * W[N,K]^T   (A row-major, W row-major "weights")
// 128x128 block tile, BK=8, 256 threads, 8x8 per thread (split 4+4 halves).
// M,N multiples of 128; K multiple of 8 (true for all calls here).
// ---------------------------------------------------------------------------
__global__ __launch_bounds__(256) void sgemm_nt(
    const float* __restrict__ A, const float* __restrict__ W,
    float* __restrict__ C, int M, int N, int K)
{
    __shared__ float As[8][128];
    __shared__ float Bs[8][128];

    const int tid = threadIdx.x;
    const int tx  = tid & 15;     // 0..15 -> n
    const int ty  = tid >> 4;     // 0..15 -> m
    const int rowBase = blockIdx.y * 128;
    const int colBase = blockIdx.x * 128;

    // loader mapping: each thread loads one float4 of A and one of W per step
    const int lr = tid >> 1;          // 0..127 (tile row)
    const int lc = (tid & 1) * 4;     // 0 or 4 (k offset)
    const float* Ap = A + (size_t)(rowBase + lr) * K + lc;
    const float* Wp = W + (size_t)(colBase + lr) * K + lc;

    float acc[8][8];
#pragma unroll
    for (int i = 0; i < 8; i++)
#pragma unroll
        for (int j = 0; j < 8; j++) acc[i][j] = 0.0f;

    for (int k0 = 0; k0 < K; k0 += 8) {
        float4 av = *(const float4*)(Ap + k0);
        float4 wv = *(const float4*)(Wp + k0);
        __syncthreads();
        As[lc+0][lr] = av.x; As[lc+1][lr] = av.y;
        As[lc+2][lr] = av.z; As[lc+3][lr] = av.w;
        Bs[lc+0][lr] = wv.x; Bs[lc+1][lr] = wv.y;
        Bs[lc+2][lr] = wv.z; Bs[lc+3][lr] = wv.w;
        __syncthreads();

#pragma unroll
        for (int kk = 0; kk < 8; kk++) {
            float a[8], b[8];
            *(float4*)&a[0] = *(const float4*)&As[kk][ty * 4];
            *(float4*)&a[4] = *(const float4*)&As[kk][64 + ty * 4];
            *(float4*)&b[0] = *(const float4*)&Bs[kk][tx * 4];
            *(float4*)&b[4] = *(const float4*)&Bs[kk][64 + tx * 4];
#pragma unroll
            for (int i = 0; i < 8; i++)
#pragma unroll
                for (int j = 0; j < 8; j++)
                    acc[i][j] = fmaf(a[i], b[j], acc[i][j]);
        }
    }

#pragma unroll
    for (int i = 0; i < 8; i++) {
        int row = rowBase + ((i < 4) ? (ty * 4 + i) : (64 + ty * 4 + i - 4));
        float4 o0 = make_float4(acc[i][0], acc[i][1], acc[i][2], acc[i][3]);
        float4 o1 = make_float4(acc[i][4], acc[i][5], acc[i][6], acc[i][7]);
        *(float4*)(C + (size_t)row * N + colBase + tx * 4)      = o0;
        *(float4*)(C + (size_t)row * N + colBase + 64 + tx * 4) = o1;
    }
}

// ---------------------------------------------------------------------------
// Fused RoPE + RMS-norm on Q and K, in place.
// One warp per (token_row, head); lane holds dims (lane) and (lane+32).
// rotate_half(x)[i]     = -x[i+32]  (i < 32)
// rotate_half(x)[i+32]  =  x[i]
// ---------------------------------------------------------------------------
__global__ __launch_bounds__(256) void rope_rms(
    float* __restrict__ Qb, float* __restrict__ Kb,
    const float* __restrict__ cp, const float* __restrict__ sp)
{
    const int gw   = (blockIdx.x * 256 + threadIdx.x) >> 5;  // global warp id
    const int lane = threadIdx.x & 31;
    const int row  = gw >> 4;       // token row 0..Mn-1
    const int head = gw & 15;
    const int t    = row & (Tn - 1);

    const float c1 = cp[t * Dn + lane];
    const float c2 = cp[t * Dn + 32 + lane];
    const float s1 = sp[t * Dn + lane];
    const float s2 = sp[t * Dn + 32 + lane];

    float* bases[2] = { Qb + (size_t)row * Cn + head * Dn,
                        Kb + (size_t)row * Cn + head * Dn };
#pragma unroll
    for (int p = 0; p < 2; p++) {
        float* base = bases[p];
        float x1 = base[lane];
        float x2 = base[lane + 32];
        float r1 = x1 * c1 - x2 * s1;   // x1*cos + (-x2)*sin
        float r2 = x2 * c2 + x1 * s2;   // x2*cos + ( x1)*sin
        float ss = r1 * r1 + r2 * r2;
#pragma unroll
        for (int off = 16; off >= 1; off >>= 1)
            ss += __shfl_xor_sync(0xffffffffu, ss, off);
        float scale = rsqrtf(ss * (1.0f / 64.0f) + 1e-6f);
        base[lane]      = r1 * scale;
        base[lane + 32] = r2 * scale;
    }
}

// ---------------------------------------------------------------------------
// Flash attention (non-causal), fp32, online softmax.
// Block = (b, h, 64-query tile). 256 threads as 16x16.
// S phase: thread (ty,tx) owns queries ty*4..+3 x keys tx*4..+3.
// O phase: thread (ty,tx) owns queries ty*4..+3 x dims tx*4..+3.
// 1/sqrt(D) folded into the Q tile at load.
// ---------------------------------------------------------------------------
#define FPAD 68
#define FLASH_SMEM (4 * 64 * FPAD * (int)sizeof(float))  // Qs,Ks,Vs,Ps = 69632 B

__global__ __launch_bounds__(256) void flash_kernel(
    const float* __restrict__ Q, const float* __restrict__ Kp,
    const float* __restrict__ V, float* __restrict__ O)
{
    extern __shared__ float sm[];
    float* Qs = sm;
    float* Ks = Qs + 64 * FPAD;
    float* Vs = Ks + 64 * FPAD;
    float* Ps = Vs + 64 * FPAD;

    const int tid = threadIdx.x;
    const int tx  = tid & 15;
    const int ty  = tid >> 4;
    const int q0  = blockIdx.x * 64;
    const int h   = blockIdx.y;
    const int b   = blockIdx.z;
    const size_t rowbase = (size_t)b * Tn;
    const int hoff = h * Dn;

    // Load Q tile, pre-scaled by 1/sqrt(64)
#pragma unroll
    for (int t = 0; t < 4; t++) {
        int i4 = tid + t * 256;          // float4 index 0..1023
        int r  = i4 >> 4;                // 0..63
        int c  = (i4 & 15) << 2;         // 0,4,...,60
        float4 v = *(const float4*)(Q + (rowbase + q0 + r) * Cn + hoff + c);
        v.x *= 0.125f; v.y *= 0.125f; v.z *= 0.125f; v.w *= 0.125f;
        *(float4*)(Qs + r * FPAD + c) = v;
    }

    float m[4], l[4], acc[4][4];
#pragma unroll
    for (int i = 0; i < 4; i++) {
        m[i] = -1e30f; l[i] = 0.0f;
#pragma unroll
        for (int j = 0; j < 4; j++) acc[i][j] = 0.0f;
    }

    for (int k0 = 0; k0 < Tn; k0 += 64) {
        __syncthreads();   // protect Ks/Vs from previous iteration's readers
#pragma unroll
        for (int t = 0; t < 4; t++) {
            int i4 = tid + t * 256;
            int r  = i4 >> 4;
            int c  = (i4 & 15) << 2;
            *(float4*)(Ks + r * FPAD + c) =
                *(const float4*)(Kp + (rowbase + k0 + r) * Cn + hoff + c);
            *(float4*)(Vs + r * FPAD + c) =
                *(const float4*)(V + (rowbase + k0 + r) * Cn + hoff + c);
        }
        __syncthreads();

        // S = Qs * Ks^T  (4x4 per thread)
        float s[4][4];
#pragma unroll
        for (int i = 0; i < 4; i++)
#pragma unroll
            for (int j = 0; j < 4; j++) s[i][j] = 0.0f;

#pragma unroll 8
        for (int d = 0; d < 64; d++) {
            float qv[4], kv[4];
#pragma unroll
            for (int i = 0; i < 4; i++) qv[i] = Qs[(ty * 4 + i) * FPAD + d];
#pragma unroll
            for (int j = 0; j < 4; j++) kv[j] = Ks[(tx * 4 + j) * FPAD + d];
#pragma unroll
            for (int i = 0; i < 4; i++)
#pragma unroll
                for (int j = 0; j < 4; j++)
                    s[i][j] = fmaf(qv[i], kv[j], s[i][j]);
        }

        // Online softmax update per query row (reduce over the 16 tx lanes)
#pragma unroll
        for (int i = 0; i < 4; i++) {
            float mx = fmaxf(fmaxf(s[i][0], s[i][1]), fmaxf(s[i][2], s[i][3]));
#pragma unroll
            for (int off = 8; off >= 1; off >>= 1)
                mx = fmaxf(mx, __shfl_xor_sync(0xffffffffu, mx, off, 16));
            float mnew  = fmaxf(m[i], mx);
            float alpha = __expf(m[i] - mnew);
            float rs = 0.0f;
#pragma unroll
            for (int j = 0; j < 4; j++) {
                s[i][j] = __expf(s[i][j] - mnew);
                rs += s[i][j];
            }
#pragma unroll
            for (int off = 8; off >= 1; off >>= 1)
                rs += __shfl_xor_sync(0xffffffffu, rs, off, 16);
            l[i] = l[i] * alpha + rs;
            m[i] = mnew;
#pragma unroll
            for (int j = 0; j < 4; j++) acc[i][j] *= alpha;
            *(float4*)(Ps + (ty * 4 + i) * FPAD + tx * 4) =
                make_float4(s[i][0], s[i][1], s[i][2], s[i][3]);
        }
        __syncthreads();

        // O += P * V   (thread now owns queries ty*4.. x dims tx*4..)
#pragma unroll 8
        for (int k = 0; k < 64; k++) {
            float pv[4], vv[4];
#pragma unroll
            for (int i = 0; i < 4; i++) pv[i] = Ps[(ty * 4 + i) * FPAD + k];
            *(float4*)&vv[0] = *(const float4*)(Vs + k * FPAD + tx * 4);
#pragma unroll
            for (int i = 0; i < 4; i++)
#pragma unroll
                for (int j = 0; j < 4; j++)
                    acc[i][j] = fmaf(pv[i], vv[j], acc[i][j]);
        }
    }

    // Epilogue: O / l  -> (b, q, h, d) packed as [Mn, Cn]
#pragma unroll
    for (int i = 0; i < 4; i++) {
        float inv = 1.0f / l[i];
        float4 o = make_float4(acc[i][0] * inv, acc[i][1] * inv,
                               acc[i][2] * inv, acc[i][3] * inv);
        *(float4*)(O + (rowbase + q0 + ty * 4 + i) * Cn + hoff + tx * 4) = o;
    }
}

// ---------------------------------------------------------------------------
extern "C" void kernel_launch(void* const* d_in, const int* in_sizes, int n_in,
                              void* d_out, int out_size)
{
    const float* x    = (const float*)d_in[0];
    const float* cosp = (const float*)d_in[1];
    const float* sinp = (const float*)d_in[2];
    const float* Wq   = (const float*)d_in[3];
    const float* Wk   = (const float*)d_in[4];
    const float* Wv   = (const float*)d_in[5];
    const float* Wo   = (const float*)d_in[6];
    float* out = (float*)d_out;

    float *gq, *gk, *gv, *ga;
    cudaGetSymbolAddress((void**)&gq, g_q);
    cudaGetSymbolAddress((void**)&gk, g_k);
    cudaGetSymbolAddress((void**)&gv, g_v);
    cudaGetSymbolAddress((void**)&ga, g_att);

    cudaFuncSetAttribute(flash_kernel,
                         cudaFuncAttributeMaxDynamicSharedMemorySize, FLASH_SMEM);

    dim3 gg(Cn / 128, Mn / 128);   // (8, 64)
    sgemm_nt<<<gg, 256>>>(x, Wq, gq, Mn, Cn, Cn);
    sgemm_nt<<<gg, 256>>>(x, Wk, gk, Mn, Cn, Cn);
    sgemm_nt<<<gg, 256>>>(x, Wv, gv, Mn, Cn, Cn);

    rope_rms<<<(Mn * Hn) / 8, 256>>>(gq, gk, cosp, sinp);

    dim3 fg(Tn / 64, Hn, Bn);      // (32, 16, 4)
    flash_kernel<<<fg, 256, FLASH_SMEM>>>(gq, gk, gv, ga);

    sgemm_nt<<<gg, 256>>>(ga, Wo, out, Mn, Cn, Cn);
}

// round 2
// speedup vs baseline: 1.3744x; 1.3744x over previous
#include <cuda_runtime.h>
#include <math.h>
#include <stdint.h>

// Problem constants
#define Bn 4
#define Tn 2048
#define Cn 1024
#define Hn 16
#define Dn 64
#define Mn (Bn*Tn)   // 8192 token rows

// Scratch (device globals; no allocation allowed)
__device__ float g_q[(size_t)Mn*Cn];
__device__ float g_k[(size_t)Mn*Cn];
__device__ float g_v[(size_t)Mn*Cn];
__device__ float g_att[(size_t)Mn*Cn];

// ---------------------------------------------------------------------------
// TF32 tensor-core GEMM: C[M,N] = A[M,K] * W[N,K]^T
// 128x128x16 CTA tile, 8 warps (2x4), 64x32 per warp, mma.m16n8k8.tf32,
// 3-stage cp.async pipeline, XOR-swizzled smem (ldmatrix conflict-free).
// ---------------------------------------------------------------------------
#define BM 128
#define BN 128
#define BK 16
#define STAGES 3
#define ATILE_BYTES (BM*BK*4)             // 8192
#define STAGE_BYTES (2*ATILE_BYTES)       // 16384 (A then W)

__device__ __forceinline__ void cp_async16(uint32_t dst, const void* src) {
    asm volatile("cp.async.cg.shared.global [%0], [%1], 16;\n" :: "r"(dst), "l"(src));
}
__device__ __forceinline__ void cp_commit() {
    asm volatile("cp.async.commit_group;\n");
}
__device__ __forceinline__ void cp_wait1() {
    asm volatile("cp.async.wait_group 1;\n");
}
__device__ __forceinline__ void ldmatrix_x4(uint32_t &r0, uint32_t &r1,
                                            uint32_t &r2, uint32_t &r3, uint32_t addr) {
    asm volatile("ldmatrix.sync.aligned.m8n8.x4.shared.b16 {%0,%1,%2,%3}, [%4];\n"
                 : "=r"(r0), "=r"(r1), "=r"(r2), "=r"(r3) : "r"(addr));
}
__device__ __forceinline__ uint32_t f2tf32(uint32_t x) {
    uint32_t y;
    asm volatile("cvt.rna.tf32.f32 %0, %1;\n" : "=r"(y) : "f"(__uint_as_float(x)));
    return y;
}
__device__ __forceinline__ void mma_tf32(float* d, const uint32_t* a, const uint32_t* b) {
    asm volatile(
        "mma.sync.aligned.m16n8k8.row.col.f32.tf32.tf32.f32 "
        "{%0,%1,%2,%3}, {%4,%5,%6,%7}, {%8,%9}, {%0,%1,%2,%3};\n"
        : "+f"(d[0]), "+f"(d[1]), "+f"(d[2]), "+f"(d[3])
        : "r"(a[0]), "r"(a[1]), "r"(a[2]), "r"(a[3]), "r"(b[0]), "r"(b[1]));
}

__global__ __launch_bounds__(256) void gemm_tf32(
    const float* __restrict__ A, const float* __restrict__ W,
    float* __restrict__ C, int M, int N, int K)
{
    __shared__ __align__(16) char smem[STAGES * STAGE_BYTES];  // 48KB

    const int tid  = threadIdx.x;
    const int lane = tid & 31;
    const int wid  = tid >> 5;
    const int wm   = wid >> 2;      // 0..1 -> 64-row slab
    const int wn   = wid & 3;       // 0..3 -> 32-col slab
    const int rowBase = blockIdx.y * BM;
    const int colBase = blockIdx.x * BN;

    const uint32_t sbase = (uint32_t)__cvta_generic_to_shared(smem);

    // ---- loader mapping: thread -> one 16B chunk per 64-row half-tile ----
    const int lr = tid >> 2;                // 0..63 (tile row, low half)
    const int lc = tid & 3;                 // chunk index 0..3 (16B each)
    const uint32_t swz = (uint32_t)(lc ^ ((lr >> 1) & 3));
    const uint32_t dA0 = sbase + (uint32_t)lr * 64 + (swz << 4);   // rows 0..63
    // rows +64: (lr+64)>>1 & 3 == lr>>1 & 3, same swizzle
    const float* pA0 = A + (size_t)(rowBase + lr) * K + lc * 4;
    const float* pA1 = A + (size_t)(rowBase + lr + 64) * K + lc * 4;
    const float* pW0 = W + (size_t)(colBase + lr) * K + lc * 4;
    const float* pW1 = W + (size_t)(colBase + lr + 64) * K + lc * 4;

    // ---- ldmatrix row addresses (precomputed) ----
    // A: 4 m-tiles of 16 rows
    uint32_t aoff[4]; uint32_t asw[4];
#pragma unroll
    for (int mt = 0; mt < 4; mt++) {
        int r = wm * 64 + mt * 16 + (lane & 15);
        aoff[mt] = (uint32_t)r * 64;
        asw[mt]  = (uint32_t)((r >> 1) & 3);
    }
    const uint32_t alo = (uint32_t)((lane >> 4) & 1);
    // B: 2 pairs of 8x8 n-tiles (16 rows each)
    uint32_t boff[2]; uint32_t bsw[2];
#pragma unroll
    for (int p = 0; p < 2; p++) {
        int r = wn * 32 + p * 16 + ((lane >> 4) << 3) + (lane & 7);
        boff[p] = (uint32_t)(ATILE_BYTES) + (uint32_t)r * 64;
        bsw[p]  = (uint32_t)((r >> 1) & 3);
    }
    const uint32_t blo = (uint32_t)((lane >> 3) & 1);

    float acc[4][4][4];
#pragma unroll
    for (int i = 0; i < 4; i++)
#pragma unroll
        for (int j = 0; j < 4; j++)
#pragma unroll
            for (int v = 0; v < 4; v++) acc[i][j][v] = 0.0f;

    const int nIters = K / BK;

    // prologue: stages 0,1
#pragma unroll
    for (int s = 0; s < 2; s++) {
        uint32_t sb = dA0 + s * STAGE_BYTES;
        int k0 = s * BK;
        cp_async16(sb,                    pA0 + k0);
        cp_async16(sb + 4096,             pA1 + k0);
        cp_async16(sb + ATILE_BYTES,      pW0 + k0);
        cp_async16(sb + ATILE_BYTES+4096, pW1 + k0);
        cp_commit();
    }

    for (int it = 0; it < nIters; ++it) {
        cp_wait1();
        __syncthreads();

        // prefetch stage it+2 into slot (it+2)%3 (== slot (it-1)%3, safe past barrier)
        if (it + 2 < nIters) {
            uint32_t sb = dA0 + ((it + 2) % STAGES) * STAGE_BYTES;
            int k0 = (it + 2) * BK;
            cp_async16(sb,                    pA0 + k0);
            cp_async16(sb + 4096,             pA1 + k0);
            cp_async16(sb + ATILE_BYTES,      pW0 + k0);
            cp_async16(sb + ATILE_BYTES+4096, pW1 + k0);
        }
        cp_commit();

        const uint32_t sb = sbase + (uint32_t)((it % STAGES) * STAGE_BYTES);
#pragma unroll
        for (int ks = 0; ks < 2; ks++) {
            uint32_t a[4][4], b[4][2];
#pragma unroll
            for (int mt = 0; mt < 4; mt++) {
                uint32_t c = (uint32_t)(2 * ks) + alo;
                uint32_t addr = sb + aoff[mt] + ((c ^ asw[mt]) << 4);
                ldmatrix_x4(a[mt][0], a[mt][1], a[mt][2], a[mt][3], addr);
            }
#pragma unroll
            for (int p = 0; p < 2; p++) {
                uint32_t c = (uint32_t)(2 * ks) + blo;
                uint32_t addr = sb + boff[p] + ((c ^ bsw[p]) << 4);
                uint32_t r0, r1, r2, r3;
                ldmatrix_x4(r0, r1, r2, r3, addr);
                b[2*p][0] = r0; b[2*p][1] = r1;
                b[2*p+1][0] = r2; b[2*p+1][1] = r3;
            }
            // round to tf32
#pragma unroll
            for (int mt = 0; mt < 4; mt++)
#pragma unroll
                for (int v = 0; v < 4; v++) a[mt][v] = f2tf32(a[mt][v]);
#pragma unroll
            for (int nt = 0; nt < 4; nt++) {
                b[nt][0] = f2tf32(b[nt][0]);
                b[nt][1] = f2tf32(b[nt][1]);
            }
#pragma unroll
            for (int mt = 0; mt < 4; mt++)
#pragma unroll
                for (int nt = 0; nt < 4; nt++)
                    mma_tf32(acc[mt][nt], a[mt], b[nt]);
        }
    }

    // epilogue
#pragma unroll
    for (int mt = 0; mt < 4; mt++) {
        int r0 = rowBase + wm * 64 + mt * 16 + (lane >> 2);
#pragma unroll
        for (int nt = 0; nt < 4; nt++) {
            int cc = colBase + wn * 32 + nt * 8 + (lane & 3) * 2;
            *(float2*)(C + (size_t)r0 * N + cc) =
                make_float2(acc[mt][nt][0], acc[mt][nt][1]);
            *(float2*)(C + (size_t)(r0 + 8) * N + cc) =
                make_float2(acc[mt][nt][2], acc[mt][nt][3]);
        }
    }
}

// ---------------------------------------------------------------------------
// Fused RoPE + RMS-norm on Q and K, in place.
// ---------------------------------------------------------------------------
__global__ __launch_bounds__(256) void rope_rms(
    float* __restrict__ Qb, float* __restrict__ Kb,
    const float* __restrict__ cp, const float* __restrict__ sp)
{
    const int gw   = (blockIdx.x * 256 + threadIdx.x) >> 5;
    const int lane = threadIdx.x & 31;
    const int row  = gw >> 4;
    const int head = gw & 15;
    const int t    = row & (Tn - 1);

    const float c1 = cp[t * Dn + lane];
    const float c2 = cp[t * Dn + 32 + lane];
    const float s1 = sp[t * Dn + lane];
    const float s2 = sp[t * Dn + 32 + lane];

    float* bases[2] = { Qb + (size_t)row * Cn + head * Dn,
                        Kb + (size_t)row * Cn + head * Dn };
#pragma unroll
    for (int p = 0; p < 2; p++) {
        float* base = bases[p];
        float x1 = base[lane];
        float x2 = base[lane + 32];
        float r1 = x1 * c1 - x2 * s1;
        float r2 = x2 * c2 + x1 * s2;
        float ss = r1 * r1 + r2 * r2;
#pragma unroll
        for (int off = 16; off >= 1; off >>= 1)
            ss += __shfl_xor_sync(0xffffffffu, ss, off);
        float scale = rsqrtf(ss * (1.0f / 64.0f) + 1e-6f);
        base[lane]      = r1 * scale;
        base[lane + 32] = r2 * scale;
    }
}

// ---------------------------------------------------------------------------
// Flash attention (non-causal), fp32, online softmax. (unchanged from R1)
// ---------------------------------------------------------------------------
#define FPAD 68
#define FLASH_SMEM (4 * 64 * FPAD * (int)sizeof(float))  // 69632 B

__global__ __launch_bounds__(256) void flash_kernel(
    const float* __restrict__ Q, const float* __restrict__ Kp,
    const float* __restrict__ V, float* __restrict__ O)
{
    extern __shared__ float sm[];
    float* Qs = sm;
    float* Ks = Qs + 64 * FPAD;
    float* Vs = Ks + 64 * FPAD;
    float* Ps = Vs + 64 * FPAD;

    const int tid = threadIdx.x;
    const int tx  = tid & 15;
    const int ty  = tid >> 4;
    const int q0  = blockIdx.x * 64;
    const int h   = blockIdx.y;
    const int b   = blockIdx.z;
    const size_t rowbase = (size_t)b * Tn;
    const int hoff = h * Dn;

#pragma unroll
    for (int t = 0; t < 4; t++) {
        int i4 = tid + t * 256;
        int r  = i4 >> 4;
        int c  = (i4 & 15) << 2;
        float4 v = *(const float4*)(Q + (rowbase + q0 + r) * Cn + hoff + c);
        v.x *= 0.125f; v.y *= 0.125f; v.z *= 0.125f; v.w *= 0.125f;
        *(float4*)(Qs + r * FPAD + c) = v;
    }

    float m[4], l[4], acc[4][4];
#pragma unroll
    for (int i = 0; i < 4; i++) {
        m[i] = -1e30f; l[i] = 0.0f;
#pragma unroll
        for (int j = 0; j < 4; j++) acc[i][j] = 0.0f;
    }

    for (int k0 = 0; k0 < Tn; k0 += 64) {
        __syncthreads();
#pragma unroll
        for (int t = 0; t < 4; t++) {
            int i4 = tid + t * 256;
            int r  = i4 >> 4;
            int c  = (i4 & 15) << 2;
            *(float4*)(Ks + r * FPAD + c) =
                *(const float4*)(Kp + (rowbase + k0 + r) * Cn + hoff + c);
            *(float4*)(Vs + r * FPAD + c) =
                *(const float4*)(V + (rowbase + k0 + r) * Cn + hoff + c);
        }
        __syncthreads();

        float s[4][4];
#pragma unroll
        for (int i = 0; i < 4; i++)
#pragma unroll
            for (int j = 0; j < 4; j++) s[i][j] = 0.0f;

#pragma unroll 8
        for (int d = 0; d < 64; d++) {
            float qv[4], kv[4];
#pragma unroll
            for (int i = 0; i < 4; i++) qv[i] = Qs[(ty * 4 + i) * FPAD + d];
#pragma unroll
            for (int j = 0; j < 4; j++) kv[j] = Ks[(tx * 4 + j) * FPAD + d];
#pragma unroll
            for (int i = 0; i < 4; i++)
#pragma unroll
                for (int j = 0; j < 4; j++)
                    s[i][j] = fmaf(qv[i], kv[j], s[i][j]);
        }

#pragma unroll
        for (int i = 0; i < 4; i++) {
            float mx = fmaxf(fmaxf(s[i][0], s[i][1]), fmaxf(s[i][2], s[i][3]));
#pragma unroll
            for (int off = 8; off >= 1; off >>= 1)
                mx = fmaxf(mx, __shfl_xor_sync(0xffffffffu, mx, off, 16));
            float mnew  = fmaxf(m[i], mx);
            float alpha = __expf(m[i] - mnew);
            float rs = 0.0f;
#pragma unroll
            for (int j = 0; j < 4; j++) {
                s[i][j] = __expf(s[i][j] - mnew);
                rs += s[i][j];
            }
#pragma unroll
            for (int off = 8; off >= 1; off >>= 1)
                rs += __shfl_xor_sync(0xffffffffu, rs, off, 16);
            l[i] = l[i] * alpha + rs;
            m[i] = mnew;
#pragma unroll
            for (int j = 0; j < 4; j++) acc[i][j] *= alpha;
            *(float4*)(Ps + (ty * 4 + i) * FPAD + tx * 4) =
                make_float4(s[i][0], s[i][1], s[i][2], s[i][3]);
        }
        __syncthreads();

#pragma unroll 8
        for (int k = 0; k < 64; k++) {
            float pv[4], vv[4];
#pragma unroll
            for (int i = 0; i < 4; i++) pv[i] = Ps[(ty * 4 + i) * FPAD + k];
            *(float4*)&vv[0] = *(const float4*)(Vs + k * FPAD + tx * 4);
#pragma unroll
            for (int i = 0; i < 4; i++)
#pragma unroll
                for (int j = 0; j < 4; j++)
                    acc[i][j] = fmaf(pv[i], vv[j], acc[i][j]);
        }
    }

#pragma unroll
    for (int i = 0; i < 4; i++) {
        float inv = 1.0f / l[i];
        float4 o = make_float4(acc[i][0] * inv, acc[i][1] * inv,
                               acc[i][2] * inv, acc[i][3] * inv);
        *(float4*)(O + (rowbase + q0 + ty * 4 + i) * Cn + hoff + tx * 4) = o;
    }
}

// ---------------------------------------------------------------------------
extern "C" void kernel_launch(void* const* d_in, const int* in_sizes, int n_in,
                              void* d_out, int out_size)
{
    const float* x    = (const float*)d_in[0];
    const float* cosp = (const float*)d_in[1];
    const float* sinp = (const float*)d_in[2];
    const float* Wq   = (const float*)d_in[3];
    const float* Wk   = (const float*)d_in[4];
    const float* Wv   = (const float*)d_in[5];
    const float* Wo   = (const float*)d_in[6];
    float* out = (float*)d_out;

    float *gq, *gk, *gv, *ga;
    cudaGetSymbolAddress((void**)&gq, g_q);
    cudaGetSymbolAddress((void**)&gk, g_k);
    cudaGetSymbolAddress((void**)&gv, g_v);
    cudaGetSymbolAddress((void**)&ga, g_att);

    cudaFuncSetAttribute(flash_kernel,
                         cudaFuncAttributeMaxDynamicSharedMemorySize, FLASH_SMEM);

    dim3 gg(Cn / 128, Mn / 128);   // (8, 64)
    gemm_tf32<<<gg, 256>>>(x, Wq, gq, Mn, Cn, Cn);
    gemm_tf32<<<gg, 256>>>(x, Wk, gk, Mn, Cn, Cn);
    gemm_tf32<<<gg, 256>>>(x, Wv, gv, Mn, Cn, Cn);

    rope_rms<<<(Mn * Hn) / 8, 256>>>(gq, gk, cosp, sinp);

    dim3 fg(Tn / 64, Hn, Bn);      // (32, 16, 4)
    flash_kernel<<<fg, 256, FLASH_SMEM>>>(gq, gk, gv, ga);

    gemm_tf32<<<gg, 256>>>(ga, Wo, out, Mn, Cn, Cn);
}